// round 13
// baseline (speedup 1.0000x reference)
#include <cuda_runtime.h>
#include <cuda_bf16.h>
#include <cstdint>
#include <math.h>

// ---------------------------------------------------------------------------
#define BB   2
#define MM   2048
#define NN   2048
#define DD   2048
#define NH   16
#define DH   128
#define DR   64
#define QK   192
#define RQ   (BB*MM)
#define RK   (BB*NN)
#define SCALE 0.07216878364870322f   // 1/sqrt(192)
#define LOG2_THETA 19.9315685693241740f

typedef __nv_bfloat16 bf16;

// ---------------------------------------------------------------------------
// Device scratch
// ---------------------------------------------------------------------------
static __device__ bf16 g_xq_h[(size_t)RQ*DD],  g_xq_l[(size_t)RQ*DD];
static __device__ bf16 g_xk_h[(size_t)RK*DD],  g_xk_l[(size_t)RK*DD];
static __device__ bf16 g_wqc_h[(size_t)DD*DD], g_wqc_l[(size_t)DD*DD];
static __device__ bf16 g_wkc_h[(size_t)DD*DD], g_wkc_l[(size_t)DD*DD];
static __device__ bf16 g_wv_h [(size_t)DD*DD], g_wv_l [(size_t)DD*DD];
static __device__ bf16 g_wo_h [(size_t)DD*DD], g_wo_l [(size_t)DD*DD];
static __device__ bf16 g_wqr_h[(size_t)NH*DR*DD], g_wqr_l[(size_t)NH*DR*DD];
static __device__ bf16 g_wkr_h[(size_t)NH*DR*DD], g_wkr_l[(size_t)NH*DR*DD];

static __device__ float g_v [(size_t)RK*DD];

static __device__ bf16 g_Q_h[(size_t)BB*NH*MM*QK], g_Q_l[(size_t)BB*NH*MM*QK];
static __device__ bf16 g_K_h[(size_t)BB*NH*NN*QK], g_K_l[(size_t)BB*NH*NN*QK];
static __device__ bf16 g_Vt_h[(size_t)BB*NH*DH*NN], g_Vt_l[(size_t)BB*NH*DH*NN];
static __device__ bf16 g_AO_h[(size_t)RQ*DD], g_AO_l[(size_t)RQ*DD];

// ---------------------------------------------------------------------------
// Helpers
// ---------------------------------------------------------------------------
__device__ __forceinline__ uint32_t smem_u32(const void* p) {
    uint32_t a;
    asm("{ .reg .u64 t; cvta.to.shared.u64 t, %1; cvt.u32.u64 %0, t; }"
        : "=r"(a) : "l"(p));
    return a;
}
__device__ __forceinline__ void ldsm_x4(uint32_t* r, uint32_t addr) {
    asm volatile("ldmatrix.sync.aligned.m8n8.x4.shared.b16 {%0,%1,%2,%3}, [%4];"
                 : "=r"(r[0]), "=r"(r[1]), "=r"(r[2]), "=r"(r[3]) : "r"(addr));
}
__device__ __forceinline__ void mma_bf16(float* d, const uint32_t* a, const uint32_t* b) {
    asm volatile(
        "mma.sync.aligned.m16n8k16.row.col.f32.bf16.bf16.f32 "
        "{%0,%1,%2,%3}, {%4,%5,%6,%7}, {%8,%9}, {%0,%1,%2,%3};"
        : "+f"(d[0]), "+f"(d[1]), "+f"(d[2]), "+f"(d[3])
        : "r"(a[0]), "r"(a[1]), "r"(a[2]), "r"(a[3]), "r"(b[0]), "r"(b[1]));
}
__device__ __forceinline__ void cp_async16(uint32_t dst, const void* src) {
    asm volatile("cp.async.cg.shared.global [%0], [%1], 16;"
                 :: "r"(dst), "l"(src) : "memory");
}
#define CP_COMMIT() asm volatile("cp.async.commit_group;" ::: "memory")
template<int N> __device__ __forceinline__ void cp_wait_n() {
    asm volatile("cp.async.wait_group %0;" :: "n"(N) : "memory");
}
__device__ __forceinline__ uint32_t pack_split(float v0, float v1, uint32_t& lo) {
    bf16 h0 = __float2bfloat16(v0), h1 = __float2bfloat16(v1);
    __nv_bfloat162 hh; hh.x = h0; hh.y = h1;
    __nv_bfloat162 ll;
    ll.x = __float2bfloat16(v0 - __bfloat162float(h0));
    ll.y = __float2bfloat16(v1 - __bfloat162float(h1));
    lo = *(uint32_t*)&ll;
    return *(uint32_t*)&hh;
}

// ---------------------------------------------------------------------------
// GEMM: unchanged from R12 (K=32 chunks, 3-stage ring, XOR swizzle, occ 2)
// ---------------------------------------------------------------------------
#define PLANE32  8192
#define STAGE32  (4*PLANE32)
#define SMEM_GEMM (3*STAGE32)

__device__ __forceinline__ uint32_t sw_addr(int row, int ec) {
    return (uint32_t)(row * 64 + (((ec >> 3) ^ ((row >> 1) & 3)) << 4));
}

__global__ __launch_bounds__(256, 2) void gemm_hmma(
    const bf16* __restrict__ Ah, const bf16* __restrict__ Al, int lda,
    const bf16* __restrict__ Bh, const bf16* __restrict__ Bl, int ldb,
    float* __restrict__ C, bf16* __restrict__ Ph_, bf16* __restrict__ Pl_,
    int ldc, int K, float scale, int mode)
{
    extern __shared__ char sm[];
    const int tid  = threadIdx.x;
    const int wid  = tid >> 5;
    const int lane = tid & 31;
    const int m0 = blockIdx.y << 7;
    const int n0 = blockIdx.x << 7;
    const int wm = (wid & 1) << 6;
    const int wn = (wid >> 1) << 5;

    const bf16* pAh = Ah + (size_t)m0 * lda;
    const bf16* pAl = Al + (size_t)m0 * lda;
    const bf16* pBh = Bh + (size_t)n0 * ldb;
    const bf16* pBl = Bl + (size_t)n0 * ldb;

    const uint32_t smb = smem_u32(sm);
    const int nc = K >> 5;

    auto load_chunk = [&](int c, int stage) {
#pragma unroll
        for (int p = 0; p < 8; ++p) {
            int id    = tid + (p << 8);
            int plane = id >> 9;
            int rem   = id & 511;
            int row   = rem >> 2;
            int cc    = rem & 3;
            const bf16* src = (plane == 0) ? pAh : (plane == 1) ? pAl
                            : (plane == 2) ? pBh : pBl;
            int ld = (plane < 2) ? lda : ldb;
            uint32_t dst = smb + stage * STAGE32 + plane * PLANE32
                         + sw_addr(row, cc << 3);
            cp_async16(dst, src + (size_t)row * ld + (c << 5) + cc * 8);
        }
        CP_COMMIT();
    };

    float acc[4][4][4];
#pragma unroll
    for (int i = 0; i < 4; ++i)
#pragma unroll
        for (int j = 0; j < 4; ++j)
#pragma unroll
            for (int q = 0; q < 4; ++q) acc[i][j][q] = 0.f;

    load_chunk(0, 0);
    load_chunk(1, 1);

    int stage = 0;
    for (int c = 0; c < nc; ++c) {
        cp_wait_n<1>();
        __syncthreads();
        if (c + 2 < nc) load_chunk(c + 2, (stage + 2 >= 3) ? stage - 1 : stage + 2);
        else            CP_COMMIT();

        const uint32_t base = smb + stage * STAGE32;
#pragma unroll
        for (int kk = 0; kk < 32; kk += 16) {
            uint32_t ah[4][4], al[4][4];
#pragma unroll
            for (int i = 0; i < 4; ++i) {
                int row = wm + i * 16 + (lane & 15);
                int ec  = kk + ((lane >> 4) << 3);
                uint32_t off = sw_addr(row, ec);
                ldsm_x4(ah[i], base + off);
                ldsm_x4(al[i], base + PLANE32 + off);
            }
            uint32_t bh[2][4], bl[2][4];
#pragma unroll
            for (int jp = 0; jp < 2; ++jp) {
                int row = wn + jp * 16 + ((lane >> 4) << 3) + (lane & 7);
                int ec  = kk + (((lane >> 3) & 1) << 3);
                uint32_t off = sw_addr(row, ec);
                ldsm_x4(bh[jp], base + 2 * PLANE32 + off);
                ldsm_x4(bl[jp], base + 3 * PLANE32 + off);
            }
#pragma unroll
            for (int i = 0; i < 4; ++i)
#pragma unroll
                for (int jp = 0; jp < 2; ++jp) {
                    mma_bf16(acc[i][2*jp],   ah[i], bh[jp]);
                    mma_bf16(acc[i][2*jp],   ah[i], bl[jp]);
                    mma_bf16(acc[i][2*jp],   al[i], bh[jp]);
                    mma_bf16(acc[i][2*jp+1], ah[i], bh[jp] + 2);
                    mma_bf16(acc[i][2*jp+1], ah[i], bl[jp] + 2);
                    mma_bf16(acc[i][2*jp+1], al[i], bh[jp] + 2);
                }
        }
        stage = (stage + 1 == 3) ? 0 : stage + 1;
    }
    cp_wait_n<0>();

    const int rbase = m0 + wm + (lane >> 2);
    const int cbase = n0 + wn + ((lane & 3) << 1);
#pragma unroll
    for (int i = 0; i < 4; ++i)
#pragma unroll
        for (int j = 0; j < 4; ++j)
#pragma unroll
            for (int hrow = 0; hrow < 2; ++hrow) {
                int r = rbase + i * 16 + hrow * 8;
                int c = cbase + j * 8;
                float v0 = acc[i][j][2*hrow + 0] * scale;
                float v1 = acc[i][j][2*hrow + 1] * scale;
                if (mode == 0) {
                    float2 f; f.x = v0; f.y = v1;
                    *(float2*)(C + (size_t)r * ldc + c) = f;
                } else if (mode == 1) {
                    int b = r >> 11, m = r & 2047;
                    size_t o = ((size_t)(b * NH + (c >> 7)) * MM + m) * QK
                             + (c & 127);
                    uint32_t lo, hi = pack_split(v0, v1, lo);
                    *(uint32_t*)(Ph_ + o) = hi;
                    *(uint32_t*)(Pl_ + o) = lo;
                } else {
                    int b = r >> 11, m = r & 2047;
                    int h = c >> 6, j2 = c & 63;
                    float inv = exp2f(-(float)j2 * (LOG2_THETA / 64.0f));
                    float sn, cs;
                    sincosf((float)m * inv, &sn, &cs);
                    float re = v0 * cs - v1 * sn;
                    float ro = v1 * cs + v0 * sn;
                    size_t o = ((size_t)(b * NH + h) * MM + m) * QK + DH + j2;
                    uint32_t lo, hi = pack_split(re, ro, lo);
                    *(uint32_t*)(Ph_ + o) = hi;
                    *(uint32_t*)(Pl_ + o) = lo;
                }
            }
}

// ---------------------------------------------------------------------------
// Flash attention — RESTRUCTURED: K=64 sub-chunks (3/tile), barrier per 96
// MMAs, 3-slot K ring (64x128B XOR-swizzled rows, cc ^= row&7), schedule
// wait<2>/sync/issue/compute; extra sync post-c2 protects slot 2; wait<7>+sync
// before PV covers V. FIFO: 4 commits + 4 consumes per tile.
// ---------------------------------------------------------------------------
#define FQ_OFF   0
#define FQ_PLANE 51200            // 128 rows * 400B
#define FK_OFF   102400
#define FK_PLANE 8192             // 64 rows * 128B
#define FK_SLOT  (2*FK_PLANE)     // 16384
#define FV_OFF   (FK_OFF + 3*FK_SLOT)   // 151552
#define FV_PLANE 18432            // 128 rows * 144B
#define FV_BUF   (2*FV_PLANE)
#define FA_SMEM  (FV_OFF + 2*FV_BUF)    // 225280

__global__ __launch_bounds__(256, 1) void flash_attn(
    const bf16* __restrict__ Qh, const bf16* __restrict__ Ql,
    const bf16* __restrict__ Kh, const bf16* __restrict__ Kl,
    const bf16* __restrict__ Vth, const bf16* __restrict__ Vtl,
    bf16* __restrict__ AOh, bf16* __restrict__ AOl)
{
    extern __shared__ char sm[];
    const int tid = threadIdx.x, wid = tid >> 5, lane = tid & 31;
    const int z  = blockIdx.y;
    const int m0 = blockIdx.x << 7;
    const uint32_t smb = smem_u32(sm);

    // K sub-chunk: 64 n-rows x 64 K-cols, both planes. Slot = c (0..2).
    auto load_k = [&](int nt, int c) {
        uint32_t base = smb + FK_OFF + c * FK_SLOT;
        int n0 = nt << 6;
#pragma unroll
        for (int p = 0; p < 4; ++p) {
            int id = tid + (p << 8);          // 0..1023
            int plane = id >> 9, rem = id & 511;
            int row = rem >> 3, cc = rem & 7;
            const bf16* src = (plane ? Kl : Kh)
                + ((size_t)z * NN + n0 + row) * QK + c * 64 + cc * 8;
            uint32_t dst = base + plane * FK_PLANE + row * 128
                         + (uint32_t)((cc ^ (row & 7)) << 4);
            cp_async16(dst, src);
        }
        CP_COMMIT();
    };
    auto load_v = [&](int nt) {
        uint32_t base = smb + FV_OFF + ((nt & 1) * FV_BUF);
        int n0 = nt << 6;
#pragma unroll
        for (int p = 0; p < 8; ++p) {
            int id = tid + (p << 8);
            int plane = id >> 10, rem = id & 1023;
            int row = rem >> 3, cc = rem & 7;
            const bf16* src = (plane ? Vtl : Vth)
                + ((size_t)z * DH + row) * NN + n0 + cc * 8;
            cp_async16(base + plane * FV_PLANE + row * 144 + cc * 16, src);
        }
        CP_COMMIT();
    };

    // prologue: Q, V0, K(0,0..2)  -> 5 groups
    {
        int row = tid & 127, plane = tid >> 7;
        const bf16* src = (plane ? Ql : Qh) + ((size_t)z * MM + m0 + row) * QK;
        uint32_t dst = smb + FQ_OFF + plane * FQ_PLANE + row * 400;
#pragma unroll
        for (int cc = 0; cc < 24; ++cc)
            cp_async16(dst + cc * 16, src + cc * 8);
        CP_COMMIT();
    }
    load_v(0); load_k(0, 0); load_k(0, 1); load_k(0, 2);

    float oacc[16][4];
#pragma unroll
    for (int j = 0; j < 16; ++j)
#pragma unroll
        for (int q = 0; q < 4; ++q) oacc[j][q] = 0.f;
    float mrow0 = -1e30f, mrow1 = -1e30f;
    float lrow0 = 0.f, lrow1 = 0.f;
    const float SC2 = SCALE * 1.4426950408889634f;

    for (int nt = 0; nt < 32; ++nt) {
        float sacc[8][4];
#pragma unroll
        for (int j = 0; j < 8; ++j)
#pragma unroll
            for (int q = 0; q < 4; ++q) sacc[j][q] = 0.f;

#pragma unroll
        for (int c = 0; c < 3; ++c) {
            cp_wait_n<2>();          // K(nt,c) complete (2 groups pending)
            __syncthreads();         // all warps done with this slot's old data
            if (c == 0)      { if (nt + 1 < 32) load_v(nt + 1);     else CP_COMMIT(); }
            else if (c == 1) { if (nt + 1 < 32) load_k(nt + 1, 0);  else CP_COMMIT(); }
            else             { if (nt + 1 < 32) load_k(nt + 1, 1);  else CP_COMMIT(); }

            uint32_t kb = smb + FK_OFF + c * FK_SLOT;
#pragma unroll
            for (int kk = 0; kk < 64; kk += 16) {
                uint32_t qh4[4], ql4[4];
                uint32_t qa = smb + FQ_OFF + (wid * 16 + (lane & 15)) * 400
                            + (c * 64 + kk + ((lane >> 4) << 3)) * 2;
                ldsm_x4(qh4, qa);
                ldsm_x4(ql4, qa + FQ_PLANE);
#pragma unroll
                for (int jp = 0; jp < 4; ++jp) {
                    uint32_t bh[4], bl[4];
                    int row = ((jp << 1) + (lane >> 4)) * 8 + (lane & 7);
                    int ec  = kk + (((lane >> 3) & 1) << 3);
                    uint32_t ka = kb + row * 128
                                + (uint32_t)((((ec >> 3) ^ (row & 7))) << 4);
                    ldsm_x4(bh, ka);
                    ldsm_x4(bl, ka + FK_PLANE);
                    mma_bf16(sacc[2*jp],   qh4, bh);
                    mma_bf16(sacc[2*jp],   qh4, bl);
                    mma_bf16(sacc[2*jp],   ql4, bh);
                    mma_bf16(sacc[2*jp+1], qh4, bh + 2);
                    mma_bf16(sacc[2*jp+1], qh4, bl + 2);
                    mma_bf16(sacc[2*jp+1], ql4, bh + 2);
                }
            }
        }
        __syncthreads();             // protect slot 2 before next-tile write
        if (nt + 1 < 32) load_k(nt + 1, 2); else CP_COMMIT();

        // ---- online softmax ----
        float rmax0 = -1e30f, rmax1 = -1e30f;
#pragma unroll
        for (int j = 0; j < 8; ++j) {
            sacc[j][0] *= SC2; sacc[j][1] *= SC2;
            sacc[j][2] *= SC2; sacc[j][3] *= SC2;
            rmax0 = fmaxf(rmax0, fmaxf(sacc[j][0], sacc[j][1]));
            rmax1 = fmaxf(rmax1, fmaxf(sacc[j][2], sacc[j][3]));
        }
#pragma unroll
        for (int o = 1; o <= 2; o <<= 1) {
            rmax0 = fmaxf(rmax0, __shfl_xor_sync(0xffffffffu, rmax0, o));
            rmax1 = fmaxf(rmax1, __shfl_xor_sync(0xffffffffu, rmax1, o));
        }
        float mn0 = fmaxf(mrow0, rmax0);
        float mn1 = fmaxf(mrow1, rmax1);
        float rs0 = exp2f(mrow0 - mn0);
        float rs1 = exp2f(mrow1 - mn1);
        mrow0 = mn0; mrow1 = mn1;
        float rsum0 = 0.f, rsum1 = 0.f;
#pragma unroll
        for (int j = 0; j < 8; ++j) {
            sacc[j][0] = exp2f(sacc[j][0] - mn0);
            sacc[j][1] = exp2f(sacc[j][1] - mn0);
            sacc[j][2] = exp2f(sacc[j][2] - mn1);
            sacc[j][3] = exp2f(sacc[j][3] - mn1);
            rsum0 += sacc[j][0] + sacc[j][1];
            rsum1 += sacc[j][2] + sacc[j][3];
        }
#pragma unroll
        for (int o = 1; o <= 2; o <<= 1) {
            rsum0 += __shfl_xor_sync(0xffffffffu, rsum0, o);
            rsum1 += __shfl_xor_sync(0xffffffffu, rsum1, o);
        }
        lrow0 = lrow0 * rs0 + rsum0;
        lrow1 = lrow1 * rs1 + rsum1;
#pragma unroll
        for (int j = 0; j < 16; ++j) {
            oacc[j][0] *= rs0; oacc[j][1] *= rs0;
            oacc[j][2] *= rs1; oacc[j][3] *= rs1;
        }

        uint32_t pfh[4][4], pfl[4][4];
#pragma unroll
        for (int s = 0; s < 4; ++s) {
            pfh[s][0] = pack_split(sacc[2*s][0],   sacc[2*s][1],   pfl[s][0]);
            pfh[s][1] = pack_split(sacc[2*s][2],   sacc[2*s][3],   pfl[s][1]);
            pfh[s][2] = pack_split(sacc[2*s+1][0], sacc[2*s+1][1], pfl[s][2]);
            pfh[s][3] = pack_split(sacc[2*s+1][2], sacc[2*s+1][3], pfl[s][3]);
        }

        // ---- PV (V(nt) guaranteed by wait<7>; sync publishes cross-thread) ----
        cp_wait_n<7>();
        __syncthreads();
        uint32_t vb = smb + FV_OFF + ((nt & 1) * FV_BUF);
#pragma unroll
        for (int s = 0; s < 4; ++s) {
#pragma unroll
            for (int dj = 0; dj < 8; ++dj) {
                uint32_t bh[4], bl[4];
                int row = ((dj << 1) + (lane >> 4)) * 8 + (lane & 7);
                int col = s * 16 + (((lane >> 3) & 1) << 3);
                uint32_t va = vb + row * 144 + col * 2;
                ldsm_x4(bh, va);
                ldsm_x4(bl, va + FV_PLANE);
                mma_bf16(oacc[2*dj],   pfh[s], bh);
                mma_bf16(oacc[2*dj],   pfh[s], bl);
                mma_bf16(oacc[2*dj],   pfl[s], bh);
                mma_bf16(oacc[2*dj+1], pfh[s], bh + 2);
                mma_bf16(oacc[2*dj+1], pfh[s], bl + 2);
                mma_bf16(oacc[2*dj+1], pfl[s], bh + 2);
            }
        }
    }

    float inv0 = 1.f / lrow0, inv1 = 1.f / lrow1;
    int b = z >> 4, hh = z & 15;
    int r0 = m0 + wid * 16 + (lane >> 2);
    int c0 = (lane & 3) << 1;
    size_t base0 = ((size_t)b * MM + r0) * DD + hh * DH;
    size_t base1 = base0 + (size_t)8 * DD;
#pragma unroll
    for (int j = 0; j < 16; ++j) {
        int d = j * 8 + c0;
        uint32_t lo;
        uint32_t hi = pack_split(oacc[j][0] * inv0, oacc[j][1] * inv0, lo);
        *(uint32_t*)(AOh + base0 + d) = hi;
        *(uint32_t*)(AOl + base0 + d) = lo;
        hi = pack_split(oacc[j][2] * inv1, oacc[j][3] * inv1, lo);
        *(uint32_t*)(AOh + base1 + d) = hi;
        *(uint32_t*)(AOl + base1 + d) = lo;
    }
}

// ---------------------------------------------------------------------------
// Fused split: all 8 input tensors, 16 floats/thread (MLP=4)
// ---------------------------------------------------------------------------
__device__ __forceinline__ void split16(const float* __restrict__ src,
                                        bf16* __restrict__ h,
                                        bf16* __restrict__ l,
                                        size_t base)
{
    float4 v[4];
#pragma unroll
    for (int q = 0; q < 4; ++q) v[q] = *(const float4*)(src + base + q * 4);
    uint32_t hw[8], lw[8];
#pragma unroll
    for (int q = 0; q < 4; ++q) {
        hw[2*q]   = pack_split(v[q].x, v[q].y, lw[2*q]);
        hw[2*q+1] = pack_split(v[q].z, v[q].w, lw[2*q+1]);
    }
#pragma unroll
    for (int q = 0; q < 2; ++q) {
        *(uint4*)(h + base + q * 8) = *(uint4*)(hw + 4*q);
        *(uint4*)(l + base + q * 8) = *(uint4*)(lw + 4*q);
    }
}

__global__ __launch_bounds__(256) void split_all(
    const float* __restrict__ query, const float* __restrict__ kv,
    const float* __restrict__ wqc,   const float* __restrict__ wkc,
    const float* __restrict__ wv,    const float* __restrict__ wqr,
    const float* __restrict__ wkr,   const float* __restrict__ wo)
{
    const int blk = blockIdx.x;
    if (blk < 2048) {
        size_t base = ((size_t)blk * 256 + threadIdx.x) * 16;
        split16(query, g_xq_h, g_xq_l, base);
    } else if (blk < 4096) {
        size_t base = ((size_t)(blk - 2048) * 256 + threadIdx.x) * 16;
        split16(kv, g_xk_h, g_xk_l, base);
    } else if (blk < 5120) {
        size_t base = ((size_t)(blk - 4096) * 256 + threadIdx.x) * 16;
        split16(wqc, g_wqc_h, g_wqc_l, base);
    } else if (blk < 6144) {
        size_t base = ((size_t)(blk - 5120) * 256 + threadIdx.x) * 16;
        split16(wkc, g_wkc_h, g_wkc_l, base);
    } else if (blk < 7168) {
        size_t base = ((size_t)(blk - 6144) * 256 + threadIdx.x) * 16;
        split16(wv, g_wv_h, g_wv_l, base);
    } else if (blk < 7680) {
        size_t base = ((size_t)(blk - 7168) * 256 + threadIdx.x) * 16;
        split16(wqr, g_wqr_h, g_wqr_l, base);
    } else if (blk < 8192) {
        size_t base = ((size_t)(blk - 7680) * 256 + threadIdx.x) * 16;
        split16(wkr, g_wkr_h, g_wkr_l, base);
    } else {
        size_t base = ((size_t)(blk - 8192) * 256 + threadIdx.x) * 16;
        split16(wo, g_wo_h, g_wo_l, base);
    }
}

// ---------------------------------------------------------------------------
__global__ void transpose_split_v(const float* __restrict__ v,
                                  bf16* __restrict__ oh, bf16* __restrict__ ol)
{
    __shared__ float t[32][33];
    const int n0 = blockIdx.x << 5;
    const int d0 = blockIdx.y << 5;
    const int z  = blockIdx.z;
    const int b  = z >> 4, h = z & 15;
#pragma unroll
    for (int r = 0; r < 4; ++r) {
        int n = n0 + threadIdx.y + r * 8;
        t[threadIdx.y + r * 8][threadIdx.x] =
            v[((size_t)b * NN + n) * DD + h * DH + d0 + threadIdx.x];
    }
    __syncthreads();
#pragma unroll
    for (int r = 0; r < 4; ++r) {
        int d = d0 + threadIdx.y + r * 8;
        int n = n0 + threadIdx.x;
        float val = t[threadIdx.x][threadIdx.y + r * 8];
        bf16 hi = __float2bfloat16(val);
        size_t o = ((size_t)z * DH + d) * NN + n;
        oh[o] = hi;
        ol[o] = __float2bfloat16(val - __bfloat162float(hi));
    }
}

// ---------------------------------------------------------------------------
extern "C" void kernel_launch(void* const* d_in, const int* in_sizes, int n_in,
                              void* d_out, int out_size)
{
    (void)in_sizes; (void)n_in; (void)out_size;
    const float* query = (const float*)d_in[0];
    const float* kv    = (const float*)d_in[1];
    const float* W_QC  = (const float*)d_in[2];
    const float* W_KC  = (const float*)d_in[3];
    const float* W_QR  = (const float*)d_in[4];
    const float* W_KR  = (const float*)d_in[5];
    const float* W_V   = (const float*)d_in[6];
    const float* W_O   = (const float*)d_in[7];
    float* out = (float*)d_out;

    bf16 *xqh,*xql,*xkh,*xkl, *wqch,*wqcl,*wkch,*wkcl, *wqrh,*wqrl,*wkrh,*wkrl;
    bf16 *wvh,*wvl, *woh,*wol, *Qh,*Ql,*Kh,*Kl, *Vth,*Vtl, *AOh,*AOl;
    float *v;
    cudaGetSymbolAddress((void**)&xqh, g_xq_h);  cudaGetSymbolAddress((void**)&xql, g_xq_l);
    cudaGetSymbolAddress((void**)&xkh, g_xk_h);  cudaGetSymbolAddress((void**)&xkl, g_xk_l);
    cudaGetSymbolAddress((void**)&wqch, g_wqc_h); cudaGetSymbolAddress((void**)&wqcl, g_wqc_l);
    cudaGetSymbolAddress((void**)&wkch, g_wkc_h); cudaGetSymbolAddress((void**)&wkcl, g_wkc_l);
    cudaGetSymbolAddress((void**)&wqrh, g_wqr_h); cudaGetSymbolAddress((void**)&wqrl, g_wqr_l);
    cudaGetSymbolAddress((void**)&wkrh, g_wkr_h); cudaGetSymbolAddress((void**)&wkrl, g_wkr_l);
    cudaGetSymbolAddress((void**)&wvh, g_wv_h);  cudaGetSymbolAddress((void**)&wvl, g_wv_l);
    cudaGetSymbolAddress((void**)&woh, g_wo_h);  cudaGetSymbolAddress((void**)&wol, g_wo_l);
    cudaGetSymbolAddress((void**)&Qh, g_Q_h);    cudaGetSymbolAddress((void**)&Ql, g_Q_l);
    cudaGetSymbolAddress((void**)&Kh, g_K_h);    cudaGetSymbolAddress((void**)&Kl, g_K_l);
    cudaGetSymbolAddress((void**)&Vth, g_Vt_h);  cudaGetSymbolAddress((void**)&Vtl, g_Vt_l);
    cudaGetSymbolAddress((void**)&AOh, g_AO_h);  cudaGetSymbolAddress((void**)&AOl, g_AO_l);
    cudaGetSymbolAddress((void**)&v,  g_v);

    cudaFuncSetAttribute(gemm_hmma, cudaFuncAttributeMaxDynamicSharedMemorySize, SMEM_GEMM);
    cudaFuncSetAttribute(flash_attn, cudaFuncAttributeMaxDynamicSharedMemorySize, FA_SMEM);

    // ---- Launch 0: all splits fused ----
    split_all<<<9216, 256>>>(query, kv, W_QC, W_KC, W_V, W_QR, W_KR, W_O);

    // ---- Launches 1-5: projections (launch #5 = V GEMM = ncu target) ----
    gemm_hmma<<<dim3(16,32),256,SMEM_GEMM>>>(xqh,xql,DD, wqch,wqcl,DD,
        nullptr, Qh, Ql, 0, DD, 1.f, 1);
    gemm_hmma<<<dim3( 8,32),256,SMEM_GEMM>>>(xqh,xql,DD, wqrh,wqrl,DD,
        nullptr, Qh, Ql, 0, DD, 1.f, 2);
    gemm_hmma<<<dim3(16,32),256,SMEM_GEMM>>>(xkh,xkl,DD, wkch,wkcl,DD,
        nullptr, Kh, Kl, 0, DD, 1.f, 1);
    gemm_hmma<<<dim3( 8,32),256,SMEM_GEMM>>>(xkh,xkl,DD, wkrh,wkrl,DD,
        nullptr, Kh, Kl, 0, DD, 1.f, 2);
    gemm_hmma<<<dim3(16,32),256,SMEM_GEMM>>>(xkh,xkl,DD, wvh,wvl,DD,
        v, nullptr, nullptr, DD, DD, 1.f, 0);

    transpose_split_v<<<dim3(NN/32, DH/32, BB*NH), dim3(32,8)>>>(v, Vth, Vtl);

    // ---- Fused attention ----
    flash_attn<<<dim3(16, 32), 256, FA_SMEM>>>(Qh, Ql, Kh, Kl, Vth, Vtl, AOh, AOl);

    // ---- Output projection ----
    gemm_hmma<<<dim3(16,32),256,SMEM_GEMM>>>(AOh,AOl,DD, woh,wol,DD,
        out, nullptr, nullptr, DD, DD, 1.f, 0);
}

// round 16
// speedup vs baseline: 1.0403x; 1.0403x over previous
#include <cuda_runtime.h>
#include <cuda_bf16.h>
#include <cstdint>
#include <math.h>

// ---------------------------------------------------------------------------
#define BB   2
#define MM   2048
#define NN   2048
#define DD   2048
#define NH   16
#define DH   128
#define DR   64
#define QK   192
#define RQ   (BB*MM)
#define RK   (BB*NN)
#define SCALE 0.07216878364870322f   // 1/sqrt(192)
#define LOG2_THETA 19.9315685693241740f

typedef __nv_bfloat16 bf16;

// ---------------------------------------------------------------------------
// Device scratch
// ---------------------------------------------------------------------------
static __device__ bf16 g_xq_h[(size_t)RQ*DD],  g_xq_l[(size_t)RQ*DD];
static __device__ bf16 g_xk_h[(size_t)RK*DD],  g_xk_l[(size_t)RK*DD];
static __device__ bf16 g_wqc_h[(size_t)DD*DD], g_wqc_l[(size_t)DD*DD];
static __device__ bf16 g_wkc_h[(size_t)DD*DD], g_wkc_l[(size_t)DD*DD];
static __device__ bf16 g_wv_h [(size_t)DD*DD], g_wv_l [(size_t)DD*DD];
static __device__ bf16 g_wo_h [(size_t)DD*DD], g_wo_l [(size_t)DD*DD];
static __device__ bf16 g_wqr_h[(size_t)NH*DR*DD], g_wqr_l[(size_t)NH*DR*DD];
static __device__ bf16 g_wkr_h[(size_t)NH*DR*DD], g_wkr_l[(size_t)NH*DR*DD];

static __device__ float g_v [(size_t)RK*DD];

static __device__ bf16 g_Q_h[(size_t)BB*NH*MM*QK], g_Q_l[(size_t)BB*NH*MM*QK];
static __device__ bf16 g_K_h[(size_t)BB*NH*NN*QK], g_K_l[(size_t)BB*NH*NN*QK];
static __device__ bf16 g_Vt_h[(size_t)BB*NH*DH*NN], g_Vt_l[(size_t)BB*NH*DH*NN];
static __device__ bf16 g_AO_h[(size_t)RQ*DD], g_AO_l[(size_t)RQ*DD];

// ---------------------------------------------------------------------------
// Helpers
// ---------------------------------------------------------------------------
__device__ __forceinline__ uint32_t smem_u32(const void* p) {
    uint32_t a;
    asm("{ .reg .u64 t; cvta.to.shared.u64 t, %1; cvt.u32.u64 %0, t; }"
        : "=r"(a) : "l"(p));
    return a;
}
__device__ __forceinline__ void ldsm_x4(uint32_t* r, uint32_t addr) {
    asm volatile("ldmatrix.sync.aligned.m8n8.x4.shared.b16 {%0,%1,%2,%3}, [%4];"
                 : "=r"(r[0]), "=r"(r[1]), "=r"(r[2]), "=r"(r[3]) : "r"(addr));
}
__device__ __forceinline__ void mma_bf16(float* d, const uint32_t* a, const uint32_t* b) {
    asm volatile(
        "mma.sync.aligned.m16n8k16.row.col.f32.bf16.bf16.f32 "
        "{%0,%1,%2,%3}, {%4,%5,%6,%7}, {%8,%9}, {%0,%1,%2,%3};"
        : "+f"(d[0]), "+f"(d[1]), "+f"(d[2]), "+f"(d[3])
        : "r"(a[0]), "r"(a[1]), "r"(a[2]), "r"(a[3]), "r"(b[0]), "r"(b[1]));
}
__device__ __forceinline__ void cp_async16(uint32_t dst, const void* src) {
    asm volatile("cp.async.cg.shared.global [%0], [%1], 16;"
                 :: "r"(dst), "l"(src) : "memory");
}
#define CP_COMMIT() asm volatile("cp.async.commit_group;" ::: "memory")
template<int N> __device__ __forceinline__ void cp_wait_n() {
    asm volatile("cp.async.wait_group %0;" :: "n"(N) : "memory");
}
__device__ __forceinline__ uint32_t pack_split(float v0, float v1, uint32_t& lo) {
    bf16 h0 = __float2bfloat16(v0), h1 = __float2bfloat16(v1);
    __nv_bfloat162 hh; hh.x = h0; hh.y = h1;
    __nv_bfloat162 ll;
    ll.x = __float2bfloat16(v0 - __bfloat162float(h0));
    ll.y = __float2bfloat16(v1 - __bfloat162float(h1));
    lo = *(uint32_t*)&ll;
    return *(uint32_t*)&hh;
}

// ---------------------------------------------------------------------------
// GEMM core (R12 structure): K=32 chunks, 3-stage ring, XOR swizzle, occ 2.
// MODE is a compile-time template parameter (0=f32, 1=cat planes, 2=rope).
// All jobs have lda=ldb=ldc=DD, K=DD, scale=1.
// ---------------------------------------------------------------------------
#define PLANE32  8192
#define STAGE32  (4*PLANE32)
#define SMEM_GEMM (3*STAGE32)

__device__ __forceinline__ uint32_t sw_addr(int row, int ec) {
    return (uint32_t)(row * 64 + (((ec >> 3) ^ ((row >> 1) & 3)) << 4));
}

template<int MODE>
__device__ __forceinline__ void gemm_core(
    char* sm,
    const bf16* __restrict__ Ah, const bf16* __restrict__ Al,
    const bf16* __restrict__ Bh, const bf16* __restrict__ Bl,
    float* __restrict__ C, bf16* __restrict__ Ph_, bf16* __restrict__ Pl_)
{
    const int tid  = threadIdx.x;
    const int wid  = tid >> 5;
    const int lane = tid & 31;
    const int m0 = blockIdx.y << 7;
    const int n0 = blockIdx.x << 7;
    const int wm = (wid & 1) << 6;
    const int wn = (wid >> 1) << 5;

    const bf16* pAh = Ah + (size_t)m0 * DD;
    const bf16* pAl = Al + (size_t)m0 * DD;
    const bf16* pBh = Bh + (size_t)n0 * DD;
    const bf16* pBl = Bl + (size_t)n0 * DD;

    const uint32_t smb = smem_u32(sm);
    const int nc = DD >> 5;          // 64 chunks of K=32

    auto load_chunk = [&](int c, int stage) {
#pragma unroll
        for (int p = 0; p < 8; ++p) {
            int id    = tid + (p << 8);
            int plane = id >> 9;
            int rem   = id & 511;
            int row   = rem >> 2;
            int cc    = rem & 3;
            const bf16* src = (plane == 0) ? pAh : (plane == 1) ? pAl
                            : (plane == 2) ? pBh : pBl;
            uint32_t dst = smb + stage * STAGE32 + plane * PLANE32
                         + sw_addr(row, cc << 3);
            cp_async16(dst, src + (size_t)row * DD + (c << 5) + cc * 8);
        }
        CP_COMMIT();
    };

    float acc[4][4][4];
#pragma unroll
    for (int i = 0; i < 4; ++i)
#pragma unroll
        for (int j = 0; j < 4; ++j)
#pragma unroll
            for (int q = 0; q < 4; ++q) acc[i][j][q] = 0.f;

    load_chunk(0, 0);
    load_chunk(1, 1);

    int stage = 0;
    for (int c = 0; c < nc; ++c) {
        cp_wait_n<1>();
        __syncthreads();
        if (c + 2 < nc) load_chunk(c + 2, (stage + 2 >= 3) ? stage - 1 : stage + 2);
        else            CP_COMMIT();

        const uint32_t base = smb + stage * STAGE32;
#pragma unroll
        for (int kk = 0; kk < 32; kk += 16) {
            uint32_t ah[4][4], al[4][4];
#pragma unroll
            for (int i = 0; i < 4; ++i) {
                int row = wm + i * 16 + (lane & 15);
                int ec  = kk + ((lane >> 4) << 3);
                uint32_t off = sw_addr(row, ec);
                ldsm_x4(ah[i], base + off);
                ldsm_x4(al[i], base + PLANE32 + off);
            }
            uint32_t bh[2][4], bl[2][4];
#pragma unroll
            for (int jp = 0; jp < 2; ++jp) {
                int row = wn + jp * 16 + ((lane >> 4) << 3) + (lane & 7);
                int ec  = kk + (((lane >> 3) & 1) << 3);
                uint32_t off = sw_addr(row, ec);
                ldsm_x4(bh[jp], base + 2 * PLANE32 + off);
                ldsm_x4(bl[jp], base + 3 * PLANE32 + off);
            }
#pragma unroll
            for (int i = 0; i < 4; ++i)
#pragma unroll
                for (int jp = 0; jp < 2; ++jp) {
                    mma_bf16(acc[i][2*jp],   ah[i], bh[jp]);
                    mma_bf16(acc[i][2*jp],   ah[i], bl[jp]);
                    mma_bf16(acc[i][2*jp],   al[i], bh[jp]);
                    mma_bf16(acc[i][2*jp+1], ah[i], bh[jp] + 2);
                    mma_bf16(acc[i][2*jp+1], ah[i], bl[jp] + 2);
                    mma_bf16(acc[i][2*jp+1], al[i], bh[jp] + 2);
                }
        }
        stage = (stage + 1 == 3) ? 0 : stage + 1;
    }
    cp_wait_n<0>();

    const int rbase = m0 + wm + (lane >> 2);
    const int cbase = n0 + wn + ((lane & 3) << 1);
#pragma unroll
    for (int i = 0; i < 4; ++i)
#pragma unroll
        for (int j = 0; j < 4; ++j)
#pragma unroll
            for (int hrow = 0; hrow < 2; ++hrow) {
                int r = rbase + i * 16 + hrow * 8;
                int c = cbase + j * 8;
                float v0 = acc[i][j][2*hrow + 0];
                float v1 = acc[i][j][2*hrow + 1];
                if (MODE == 0) {
                    float2 f; f.x = v0; f.y = v1;
                    *(float2*)(C + (size_t)r * DD + c) = f;
                } else if (MODE == 1) {
                    int b = r >> 11, m = r & 2047;
                    size_t o = ((size_t)(b * NH + (c >> 7)) * MM + m) * QK
                             + (c & 127);
                    uint32_t lo, hi = pack_split(v0, v1, lo);
                    *(uint32_t*)(Ph_ + o) = hi;
                    *(uint32_t*)(Pl_ + o) = lo;
                } else {
                    int b = r >> 11, m = r & 2047;
                    int h = c >> 6, j2 = c & 63;
                    float inv = exp2f(-(float)j2 * (LOG2_THETA / 64.0f));
                    float sn, cs;
                    sincosf((float)m * inv, &sn, &cs);
                    float re = v0 * cs - v1 * sn;
                    float ro = v1 * cs + v0 * sn;
                    size_t o = ((size_t)(b * NH + h) * MM + m) * QK + DH + j2;
                    uint32_t lo, hi = pack_split(re, ro, lo);
                    *(uint32_t*)(Ph_ + o) = hi;
                    *(uint32_t*)(Pl_ + o) = lo;
                }
            }
}

// Paired mode-1 (cat) launch: z=0 -> (xq,wqc)->Q planes, z=1 -> (xk,wkc)->K
__global__ __launch_bounds__(256, 2) void gemm_cat2()
{
    extern __shared__ char sm[];
    if (blockIdx.z == 0)
        gemm_core<1>(sm, g_xq_h, g_xq_l, g_wqc_h, g_wqc_l, nullptr, g_Q_h, g_Q_l);
    else
        gemm_core<1>(sm, g_xk_h, g_xk_l, g_wkc_h, g_wkc_l, nullptr, g_K_h, g_K_l);
}
// Paired mode-2 (rope) launch: z=0 -> (xq,wqr)->Q planes, z=1 -> (xk,wkr)->K
__global__ __launch_bounds__(256, 2) void gemm_rope2()
{
    extern __shared__ char sm[];
    if (blockIdx.z == 0)
        gemm_core<2>(sm, g_xq_h, g_xq_l, g_wqr_h, g_wqr_l, nullptr, g_Q_h, g_Q_l);
    else
        gemm_core<2>(sm, g_xk_h, g_xk_l, g_wkr_h, g_wkr_l, nullptr, g_K_h, g_K_l);
}
// Mode-0 f32 output GEMMs (V and WO)
__global__ __launch_bounds__(256, 2) void gemm_v()
{
    extern __shared__ char sm[];
    gemm_core<0>(sm, g_xk_h, g_xk_l, g_wv_h, g_wv_l, g_v, nullptr, nullptr);
}
__global__ __launch_bounds__(256, 2) void gemm_wo(float* __restrict__ out)
{
    extern __shared__ char sm[];
    gemm_core<0>(sm, g_AO_h, g_AO_l, g_wo_h, g_wo_l, out, nullptr, nullptr);
}

// ---------------------------------------------------------------------------
// Flash attention (R13 version, unchanged)
// ---------------------------------------------------------------------------
#define FQ_OFF   0
#define FQ_PLANE 51200
#define FK_OFF   102400
#define FK_PLANE 8192
#define FK_SLOT  (2*FK_PLANE)
#define FV_OFF   (FK_OFF + 3*FK_SLOT)
#define FV_PLANE 18432
#define FV_BUF   (2*FV_PLANE)
#define FA_SMEM  (FV_OFF + 2*FV_BUF)

__global__ __launch_bounds__(256, 1) void flash_attn(
    const bf16* __restrict__ Qh, const bf16* __restrict__ Ql,
    const bf16* __restrict__ Kh, const bf16* __restrict__ Kl,
    const bf16* __restrict__ Vth, const bf16* __restrict__ Vtl,
    bf16* __restrict__ AOh, bf16* __restrict__ AOl)
{
    extern __shared__ char sm[];
    const int tid = threadIdx.x, wid = tid >> 5, lane = tid & 31;
    const int z  = blockIdx.y;
    const int m0 = blockIdx.x << 7;
    const uint32_t smb = smem_u32(sm);

    auto load_k = [&](int nt, int c) {
        uint32_t base = smb + FK_OFF + c * FK_SLOT;
        int n0 = nt << 6;
#pragma unroll
        for (int p = 0; p < 4; ++p) {
            int id = tid + (p << 8);
            int plane = id >> 9, rem = id & 511;
            int row = rem >> 3, cc = rem & 7;
            const bf16* src = (plane ? Kl : Kh)
                + ((size_t)z * NN + n0 + row) * QK + c * 64 + cc * 8;
            uint32_t dst = base + plane * FK_PLANE + row * 128
                         + (uint32_t)((cc ^ (row & 7)) << 4);
            cp_async16(dst, src);
        }
        CP_COMMIT();
    };
    auto load_v = [&](int nt) {
        uint32_t base = smb + FV_OFF + ((nt & 1) * FV_BUF);
        int n0 = nt << 6;
#pragma unroll
        for (int p = 0; p < 8; ++p) {
            int id = tid + (p << 8);
            int plane = id >> 10, rem = id & 1023;
            int row = rem >> 3, cc = rem & 7;
            const bf16* src = (plane ? Vtl : Vth)
                + ((size_t)z * DH + row) * NN + n0 + cc * 8;
            cp_async16(base + plane * FV_PLANE + row * 144 + cc * 16, src);
        }
        CP_COMMIT();
    };

    {
        int row = tid & 127, plane = tid >> 7;
        const bf16* src = (plane ? Ql : Qh) + ((size_t)z * MM + m0 + row) * QK;
        uint32_t dst = smb + FQ_OFF + plane * FQ_PLANE + row * 400;
#pragma unroll
        for (int cc = 0; cc < 24; ++cc)
            cp_async16(dst + cc * 16, src + cc * 8);
        CP_COMMIT();
    }
    load_v(0); load_k(0, 0); load_k(0, 1); load_k(0, 2);

    float oacc[16][4];
#pragma unroll
    for (int j = 0; j < 16; ++j)
#pragma unroll
        for (int q = 0; q < 4; ++q) oacc[j][q] = 0.f;
    float mrow0 = -1e30f, mrow1 = -1e30f;
    float lrow0 = 0.f, lrow1 = 0.f;
    const float SC2 = SCALE * 1.4426950408889634f;

    for (int nt = 0; nt < 32; ++nt) {
        float sacc[8][4];
#pragma unroll
        for (int j = 0; j < 8; ++j)
#pragma unroll
            for (int q = 0; q < 4; ++q) sacc[j][q] = 0.f;

#pragma unroll
        for (int c = 0; c < 3; ++c) {
            cp_wait_n<2>();
            __syncthreads();
            if (c == 0)      { if (nt + 1 < 32) load_v(nt + 1);     else CP_COMMIT(); }
            else if (c == 1) { if (nt + 1 < 32) load_k(nt + 1, 0);  else CP_COMMIT(); }
            else             { if (nt + 1 < 32) load_k(nt + 1, 1);  else CP_COMMIT(); }

            uint32_t kb = smb + FK_OFF + c * FK_SLOT;
#pragma unroll
            for (int kk = 0; kk < 64; kk += 16) {
                uint32_t qh4[4], ql4[4];
                uint32_t qa = smb + FQ_OFF + (wid * 16 + (lane & 15)) * 400
                            + (c * 64 + kk + ((lane >> 4) << 3)) * 2;
                ldsm_x4(qh4, qa);
                ldsm_x4(ql4, qa + FQ_PLANE);
#pragma unroll
                for (int jp = 0; jp < 4; ++jp) {
                    uint32_t bh[4], bl[4];
                    int row = ((jp << 1) + (lane >> 4)) * 8 + (lane & 7);
                    int ec  = kk + (((lane >> 3) & 1) << 3);
                    uint32_t ka = kb + row * 128
                                + (uint32_t)((((ec >> 3) ^ (row & 7))) << 4);
                    ldsm_x4(bh, ka);
                    ldsm_x4(bl, ka + FK_PLANE);
                    mma_bf16(sacc[2*jp],   qh4, bh);
                    mma_bf16(sacc[2*jp],   qh4, bl);
                    mma_bf16(sacc[2*jp],   ql4, bh);
                    mma_bf16(sacc[2*jp+1], qh4, bh + 2);
                    mma_bf16(sacc[2*jp+1], qh4, bl + 2);
                    mma_bf16(sacc[2*jp+1], ql4, bh + 2);
                }
            }
        }
        __syncthreads();
        if (nt + 1 < 32) load_k(nt + 1, 2); else CP_COMMIT();

        float rmax0 = -1e30f, rmax1 = -1e30f;
#pragma unroll
        for (int j = 0; j < 8; ++j) {
            sacc[j][0] *= SC2; sacc[j][1] *= SC2;
            sacc[j][2] *= SC2; sacc[j][3] *= SC2;
            rmax0 = fmaxf(rmax0, fmaxf(sacc[j][0], sacc[j][1]));
            rmax1 = fmaxf(rmax1, fmaxf(sacc[j][2], sacc[j][3]));
        }
#pragma unroll
        for (int o = 1; o <= 2; o <<= 1) {
            rmax0 = fmaxf(rmax0, __shfl_xor_sync(0xffffffffu, rmax0, o));
            rmax1 = fmaxf(rmax1, __shfl_xor_sync(0xffffffffu, rmax1, o));
        }
        float mn0 = fmaxf(mrow0, rmax0);
        float mn1 = fmaxf(mrow1, rmax1);
        float rs0 = exp2f(mrow0 - mn0);
        float rs1 = exp2f(mrow1 - mn1);
        mrow0 = mn0; mrow1 = mn1;
        float rsum0 = 0.f, rsum1 = 0.f;
#pragma unroll
        for (int j = 0; j < 8; ++j) {
            sacc[j][0] = exp2f(sacc[j][0] - mn0);
            sacc[j][1] = exp2f(sacc[j][1] - mn0);
            sacc[j][2] = exp2f(sacc[j][2] - mn1);
            sacc[j][3] = exp2f(sacc[j][3] - mn1);
            rsum0 += sacc[j][0] + sacc[j][1];
            rsum1 += sacc[j][2] + sacc[j][3];
        }
#pragma unroll
        for (int o = 1; o <= 2; o <<= 1) {
            rsum0 += __shfl_xor_sync(0xffffffffu, rsum0, o);
            rsum1 += __shfl_xor_sync(0xffffffffu, rsum1, o);
        }
        lrow0 = lrow0 * rs0 + rsum0;
        lrow1 = lrow1 * rs1 + rsum1;
#pragma unroll
        for (int j = 0; j < 16; ++j) {
            oacc[j][0] *= rs0; oacc[j][1] *= rs0;
            oacc[j][2] *= rs1; oacc[j][3] *= rs1;
        }

        uint32_t pfh[4][4], pfl[4][4];
#pragma unroll
        for (int s = 0; s < 4; ++s) {
            pfh[s][0] = pack_split(sacc[2*s][0],   sacc[2*s][1],   pfl[s][0]);
            pfh[s][1] = pack_split(sacc[2*s][2],   sacc[2*s][3],   pfl[s][1]);
            pfh[s][2] = pack_split(sacc[2*s+1][0], sacc[2*s+1][1], pfl[s][2]);
            pfh[s][3] = pack_split(sacc[2*s+1][2], sacc[2*s+1][3], pfl[s][3]);
        }

        cp_wait_n<7>();
        __syncthreads();
        uint32_t vb = smb + FV_OFF + ((nt & 1) * FV_BUF);
#pragma unroll
        for (int s = 0; s < 4; ++s) {
#pragma unroll
            for (int dj = 0; dj < 8; ++dj) {
                uint32_t bh[4], bl[4];
                int row = ((dj << 1) + (lane >> 4)) * 8 + (lane & 7);
                int col = s * 16 + (((lane >> 3) & 1) << 3);
                uint32_t va = vb + row * 144 + col * 2;
                ldsm_x4(bh, va);
                ldsm_x4(bl, va + FV_PLANE);
                mma_bf16(oacc[2*dj],   pfh[s], bh);
                mma_bf16(oacc[2*dj],   pfh[s], bl);
                mma_bf16(oacc[2*dj],   pfl[s], bh);
                mma_bf16(oacc[2*dj+1], pfh[s], bh + 2);
                mma_bf16(oacc[2*dj+1], pfh[s], bl + 2);
                mma_bf16(oacc[2*dj+1], pfl[s], bh + 2);
            }
        }
    }

    float inv0 = 1.f / lrow0, inv1 = 1.f / lrow1;
    int b = z >> 4, hh = z & 15;
    int r0 = m0 + wid * 16 + (lane >> 2);
    int c0 = (lane & 3) << 1;
    size_t base0 = ((size_t)b * MM + r0) * DD + hh * DH;
    size_t base1 = base0 + (size_t)8 * DD;
#pragma unroll
    for (int j = 0; j < 16; ++j) {
        int d = j * 8 + c0;
        uint32_t lo;
        uint32_t hi = pack_split(oacc[j][0] * inv0, oacc[j][1] * inv0, lo);
        *(uint32_t*)(AOh + base0 + d) = hi;
        *(uint32_t*)(AOl + base0 + d) = lo;
        hi = pack_split(oacc[j][2] * inv1, oacc[j][3] * inv1, lo);
        *(uint32_t*)(AOh + base1 + d) = hi;
        *(uint32_t*)(AOl + base1 + d) = lo;
    }
}

// ---------------------------------------------------------------------------
// Fused split: all 8 input tensors, 16 floats/thread (MLP=4)
// ---------------------------------------------------------------------------
__device__ __forceinline__ void split16(const float* __restrict__ src,
                                        bf16* __restrict__ h,
                                        bf16* __restrict__ l,
                                        size_t base)
{
    float4 v[4];
#pragma unroll
    for (int q = 0; q < 4; ++q) v[q] = *(const float4*)(src + base + q * 4);
    uint32_t hw[8], lw[8];
#pragma unroll
    for (int q = 0; q < 4; ++q) {
        hw[2*q]   = pack_split(v[q].x, v[q].y, lw[2*q]);
        hw[2*q+1] = pack_split(v[q].z, v[q].w, lw[2*q+1]);
    }
#pragma unroll
    for (int q = 0; q < 2; ++q) {
        *(uint4*)(h + base + q * 8) = *(uint4*)(hw + 4*q);
        *(uint4*)(l + base + q * 8) = *(uint4*)(lw + 4*q);
    }
}

__global__ __launch_bounds__(256) void split_all(
    const float* __restrict__ query, const float* __restrict__ kv,
    const float* __restrict__ wqc,   const float* __restrict__ wkc,
    const float* __restrict__ wv,    const float* __restrict__ wqr,
    const float* __restrict__ wkr,   const float* __restrict__ wo)
{
    const int blk = blockIdx.x;
    if (blk < 2048) {
        size_t base = ((size_t)blk * 256 + threadIdx.x) * 16;
        split16(query, g_xq_h, g_xq_l, base);
    } else if (blk < 4096) {
        size_t base = ((size_t)(blk - 2048) * 256 + threadIdx.x) * 16;
        split16(kv, g_xk_h, g_xk_l, base);
    } else if (blk < 5120) {
        size_t base = ((size_t)(blk - 4096) * 256 + threadIdx.x) * 16;
        split16(wqc, g_wqc_h, g_wqc_l, base);
    } else if (blk < 6144) {
        size_t base = ((size_t)(blk - 5120) * 256 + threadIdx.x) * 16;
        split16(wkc, g_wkc_h, g_wkc_l, base);
    } else if (blk < 7168) {
        size_t base = ((size_t)(blk - 6144) * 256 + threadIdx.x) * 16;
        split16(wv, g_wv_h, g_wv_l, base);
    } else if (blk < 7680) {
        size_t base = ((size_t)(blk - 7168) * 256 + threadIdx.x) * 16;
        split16(wqr, g_wqr_h, g_wqr_l, base);
    } else if (blk < 8192) {
        size_t base = ((size_t)(blk - 7680) * 256 + threadIdx.x) * 16;
        split16(wkr, g_wkr_h, g_wkr_l, base);
    } else {
        size_t base = ((size_t)(blk - 8192) * 256 + threadIdx.x) * 16;
        split16(wo, g_wo_h, g_wo_l, base);
    }
}

// ---------------------------------------------------------------------------
__global__ void transpose_split_v(const float* __restrict__ v,
                                  bf16* __restrict__ oh, bf16* __restrict__ ol)
{
    __shared__ float t[32][33];
    const int n0 = blockIdx.x << 5;
    const int d0 = blockIdx.y << 5;
    const int z  = blockIdx.z;
    const int b  = z >> 4, h = z & 15;
#pragma unroll
    for (int r = 0; r < 4; ++r) {
        int n = n0 + threadIdx.y + r * 8;
        t[threadIdx.y + r * 8][threadIdx.x] =
            v[((size_t)b * NN + n) * DD + h * DH + d0 + threadIdx.x];
    }
    __syncthreads();
#pragma unroll
    for (int r = 0; r < 4; ++r) {
        int d = d0 + threadIdx.y + r * 8;
        int n = n0 + threadIdx.x;
        float val = t[threadIdx.x][threadIdx.y + r * 8];
        bf16 hi = __float2bfloat16(val);
        size_t o = ((size_t)z * DH + d) * NN + n;
        oh[o] = hi;
        ol[o] = __float2bfloat16(val - __bfloat162float(hi));
    }
}

// ---------------------------------------------------------------------------
extern "C" void kernel_launch(void* const* d_in, const int* in_sizes, int n_in,
                              void* d_out, int out_size)
{
    (void)in_sizes; (void)n_in; (void)out_size;
    const float* query = (const float*)d_in[0];
    const float* kv    = (const float*)d_in[1];
    const float* W_QC  = (const float*)d_in[2];
    const float* W_KC  = (const float*)d_in[3];
    const float* W_QR  = (const float*)d_in[4];
    const float* W_KR  = (const float*)d_in[5];
    const float* W_V   = (const float*)d_in[6];
    const float* W_O   = (const float*)d_in[7];
    float* out = (float*)d_out;

    bf16 *Qh,*Ql,*Kh,*Kl, *Vth,*Vtl, *AOh,*AOl;
    float *v;
    cudaGetSymbolAddress((void**)&Qh, g_Q_h);    cudaGetSymbolAddress((void**)&Ql, g_Q_l);
    cudaGetSymbolAddress((void**)&Kh, g_K_h);    cudaGetSymbolAddress((void**)&Kl, g_K_l);
    cudaGetSymbolAddress((void**)&Vth, g_Vt_h);  cudaGetSymbolAddress((void**)&Vtl, g_Vt_l);
    cudaGetSymbolAddress((void**)&AOh, g_AO_h);  cudaGetSymbolAddress((void**)&AOl, g_AO_l);
    cudaGetSymbolAddress((void**)&v,  g_v);

    cudaFuncSetAttribute(gemm_cat2,  cudaFuncAttributeMaxDynamicSharedMemorySize, SMEM_GEMM);
    cudaFuncSetAttribute(gemm_rope2, cudaFuncAttributeMaxDynamicSharedMemorySize, SMEM_GEMM);
    cudaFuncSetAttribute(gemm_v,     cudaFuncAttributeMaxDynamicSharedMemorySize, SMEM_GEMM);
    cudaFuncSetAttribute(gemm_wo,    cudaFuncAttributeMaxDynamicSharedMemorySize, SMEM_GEMM);
    cudaFuncSetAttribute(flash_attn, cudaFuncAttributeMaxDynamicSharedMemorySize, FA_SMEM);

    // ---- Launch 0: all splits fused ----
    split_all<<<9216, 256>>>(query, kv, W_QC, W_KC, W_V, W_QR, W_KR, W_O);

    // ---- Launch 1-3: merged projection pairs + V ----
    gemm_cat2 <<<dim3(16,32,2), 256, SMEM_GEMM>>>();
    gemm_rope2<<<dim3( 8,32,2), 256, SMEM_GEMM>>>();
    gemm_v    <<<dim3(16,32),   256, SMEM_GEMM>>>();

    // ---- Launch 4: V transpose+split ----
    transpose_split_v<<<dim3(NN/32, DH/32, BB*NH), dim3(32,8)>>>(v, Vth, Vtl);

    // ---- Launch 5: fused attention (ncu target this round) ----
    flash_attn<<<dim3(16, 32), 256, FA_SMEM>>>(Qh, Ql, Kh, Kl, Vth, Vtl, AOh, AOl);

    // ---- Launch 6: output projection ----
    gemm_wo<<<dim3(16,32), 256, SMEM_GEMM>>>(out);
}